// round 2
// baseline (speedup 1.0000x reference)
#include <cuda_runtime.h>
#include <cuda_fp16.h>

#define C 128
#define NUM_ITERS 10
#define MAXN 500000

// Tiny scratch state + fp16 exp(S) cache (all __device__ globals: no allocation).
__device__ __align__(16) float g_v[2][C];   // ping-pong col-scaling vectors
__device__ float g_b[C];                    // b = ratios * total_num
__device__ float g_colsum[C];               // global column-sum accumulator
__device__ uint4 g_E[(size_t)MAXN * (C / 8)];  // E = exp(S) as fp16, 8 halves per uint4

// ---------------------------------------------------------------------------
// init: b = ratios * total_num ; v0 = 1 ; colsum = 0
// ---------------------------------------------------------------------------
__global__ void init_k(const float* __restrict__ ratios,
                       const int* __restrict__ total_num) {
    int j = threadIdx.x;
    float tn = (float)(*total_num);
    g_b[j] = ratios[j] * tn;
    g_v[0][j] = 1.0f;
    g_v[1][j] = 1.0f;
    g_colsum[j] = 0.0f;
}

// ---------------------------------------------------------------------------
// Pass 1 (fused): read S fp32, E=exp(S) -> store fp16, and do iteration 1
// (v0 = 1). One warp per row, lane owns 4 cols via float4.
// ---------------------------------------------------------------------------
__global__ void __launch_bounds__(256)
pass1_k(const float4* __restrict__ S4, int N) {
    const int lane = threadIdx.x & 31;
    const int gwarp = blockIdx.x * (blockDim.x >> 5) + (threadIdx.x >> 5);
    const int nwarps = gridDim.x * (blockDim.x >> 5);

    float4 v = reinterpret_cast<const float4*>(g_v[0])[lane];
    float c0 = 0.f, c1 = 0.f, c2 = 0.f, c3 = 0.f;
    uint2* __restrict__ E2 = reinterpret_cast<uint2*>(g_E);

    for (int row = gwarp; row < N; row += nwarps) {
        float4 s = S4[(size_t)row * 32 + lane];
        float e0 = __expf(s.x);
        float e1 = __expf(s.y);
        float e2 = __expf(s.z);
        float e3 = __expf(s.w);

        __half2 h01 = __floats2half2_rn(e0, e1);
        __half2 h23 = __floats2half2_rn(e2, e3);
        uint2 pk;
        pk.x = *reinterpret_cast<unsigned*>(&h01);
        pk.y = *reinterpret_cast<unsigned*>(&h23);
        E2[(size_t)row * 32 + lane] = pk;

        float p = fmaf(e0, v.x, fmaf(e1, v.y, fmaf(e2, v.z, e3 * v.w)));
        #pragma unroll
        for (int o = 16; o; o >>= 1)
            p += __shfl_xor_sync(0xffffffffu, p, o);
        float u = 1.0f / p;
        c0 = fmaf(u, e0, c0);
        c1 = fmaf(u, e1, c1);
        c2 = fmaf(u, e2, c2);
        c3 = fmaf(u, e3, c3);
    }

    __shared__ float scol[C];
    if (threadIdx.x < C) scol[threadIdx.x] = 0.0f;
    __syncthreads();
    int col = lane * 4;
    atomicAdd(&scol[col + 0], c0);
    atomicAdd(&scol[col + 1], c1);
    atomicAdd(&scol[col + 2], c2);
    atomicAdd(&scol[col + 3], c3);
    __syncthreads();
    if (threadIdx.x < C)
        atomicAdd(&g_colsum[threadIdx.x], scol[threadIdx.x]);
}

// ---------------------------------------------------------------------------
// Iterations 2..10: read fp16 E only. 16 lanes per row (8 cols each via
// uint4 of 8 halves), 2 rows per warp per load. No exp; 1 rcp per row.
// ---------------------------------------------------------------------------
__global__ void __launch_bounds__(256)
iterh_k(int NP2, int parity_in) {
    const int lane = threadIdx.x & 31;
    const int sub = lane & 15;   // position within row (8 cols each)
    const int gwarp = blockIdx.x * (blockDim.x >> 5) + (threadIdx.x >> 5);
    const int nwarps = gridDim.x * (blockDim.x >> 5);

    // this lane's 8 v values: cols sub*8 .. sub*8+7
    float4 va = reinterpret_cast<const float4*>(g_v[parity_in])[sub * 2];
    float4 vb = reinterpret_cast<const float4*>(g_v[parity_in])[sub * 2 + 1];

    float c[8];
    #pragma unroll
    for (int k = 0; k < 8; ++k) c[k] = 0.0f;

    for (int rp = gwarp; rp < NP2; rp += nwarps) {
        uint4 q = g_E[(size_t)rp * 32 + lane];
        float2 f0 = __half22float2(*reinterpret_cast<__half2*>(&q.x));
        float2 f1 = __half22float2(*reinterpret_cast<__half2*>(&q.y));
        float2 f2 = __half22float2(*reinterpret_cast<__half2*>(&q.z));
        float2 f3 = __half22float2(*reinterpret_cast<__half2*>(&q.w));

        float p = fmaf(f0.x, va.x,
                  fmaf(f0.y, va.y,
                  fmaf(f1.x, va.z,
                  fmaf(f1.y, va.w,
                  fmaf(f2.x, vb.x,
                  fmaf(f2.y, vb.y,
                  fmaf(f3.x, vb.z, f3.y * vb.w)))))));
        // reduce over the 16 lanes of this row (xor 8,4,2,1 stays in group)
        p += __shfl_xor_sync(0xffffffffu, p, 8);
        p += __shfl_xor_sync(0xffffffffu, p, 4);
        p += __shfl_xor_sync(0xffffffffu, p, 2);
        p += __shfl_xor_sync(0xffffffffu, p, 1);
        float u = 1.0f / p;

        c[0] = fmaf(u, f0.x, c[0]);
        c[1] = fmaf(u, f0.y, c[1]);
        c[2] = fmaf(u, f1.x, c[2]);
        c[3] = fmaf(u, f1.y, c[3]);
        c[4] = fmaf(u, f2.x, c[4]);
        c[5] = fmaf(u, f2.y, c[5]);
        c[6] = fmaf(u, f3.x, c[6]);
        c[7] = fmaf(u, f3.y, c[7]);
    }

    __shared__ float scol[C];
    if (threadIdx.x < C) scol[threadIdx.x] = 0.0f;
    __syncthreads();
    int cb = sub * 8;
    #pragma unroll
    for (int k = 0; k < 8; ++k)
        atomicAdd(&scol[cb + k], c[k]);
    __syncthreads();
    if (threadIdx.x < C)
        atomicAdd(&g_colsum[threadIdx.x], scol[threadIdx.x]);
}

// ---------------------------------------------------------------------------
// v_out[j] = b[j] / colsum[j] ; reset colsum for next iteration
// ---------------------------------------------------------------------------
__global__ void vnorm_k(int parity_out) {
    int j = threadIdx.x;
    g_v[parity_out][j] = g_b[j] / g_colsum[j];
    g_colsum[j] = 0.0f;
}

// ---------------------------------------------------------------------------
// Final pass from fp32 S (full output precision):
// P_ij = u_i * exp(S_ij) * v10[j], u_i = 1/sum_j exp(S_ij)*v9[j]
// ---------------------------------------------------------------------------
__global__ void __launch_bounds__(256)
final_k(const float4* __restrict__ S4, float4* __restrict__ out, int N) {
    const int lane = threadIdx.x & 31;
    const int gwarp = blockIdx.x * (blockDim.x >> 5) + (threadIdx.x >> 5);
    const int nwarps = gridDim.x * (blockDim.x >> 5);

    float4 v9  = reinterpret_cast<const float4*>(g_v[1])[lane];
    float4 v10 = reinterpret_cast<const float4*>(g_v[0])[lane];

    for (int row = gwarp; row < N; row += nwarps) {
        float4 s = S4[(size_t)row * 32 + lane];
        float e0 = __expf(s.x);
        float e1 = __expf(s.y);
        float e2 = __expf(s.z);
        float e3 = __expf(s.w);
        float p = fmaf(e0, v9.x, fmaf(e1, v9.y, fmaf(e2, v9.z, e3 * v9.w)));
        #pragma unroll
        for (int o = 16; o; o >>= 1)
            p += __shfl_xor_sync(0xffffffffu, p, o);
        float u = 1.0f / p;
        float4 o4;
        o4.x = u * e0 * v10.x;
        o4.y = u * e1 * v10.y;
        o4.z = u * e2 * v10.z;
        o4.w = u * e3 * v10.w;
        out[(size_t)row * 32 + lane] = o4;
    }
}

// ---------------------------------------------------------------------------
// Inputs (metadata order): 0 features (unused), 1 text_features (unused),
// 2 sim_matrix_whole [N,128] f32, 3 ratios [128] f32, 4 targets (unused),
// 5 total_num scalar i32. Output: P [N,128] f32.
// ---------------------------------------------------------------------------
extern "C" void kernel_launch(void* const* d_in, const int* in_sizes, int n_in,
                              void* d_out, int out_size) {
    const float* S        = (const float*)d_in[2];
    const float* ratios   = (const float*)d_in[3];
    const int*   totalnum = (const int*)d_in[5];
    const int N = in_sizes[2] / C;

    const int GRID = 1184;   // 148 SMs * 8 blocks, grid-stride
    const int BLK  = 256;

    init_k<<<1, C>>>(ratios, totalnum);

    // Iteration 1 fused with exp + fp16 E store (reads S once).
    pass1_k<<<GRID, BLK>>>((const float4*)S, N);
    vnorm_k<<<1, C>>>(1);   // v1 -> g_v[1]

    // Iterations 2..10 read only the fp16 E cache.
    for (int t = 2; t <= NUM_ITERS; ++t) {
        iterh_k<<<GRID, BLK>>>(N / 2, (t - 1) & 1);
        vnorm_k<<<1, C>>>(t & 1);
    }

    // Final output from fp32 S: v9 in g_v[1], v10 in g_v[0].
    final_k<<<GRID, BLK>>>((const float4*)S, (float4*)d_out, N);
}

// round 3
// speedup vs baseline: 1.3435x; 1.3435x over previous
#include <cuda_runtime.h>
#include <cuda_fp16.h>

#define C 128
#define NUM_ITERS 10
#define MAXN 500000

// Scratch (__device__ globals, no allocation).
__device__ float g_b[C];                        // b = ratios * total_num
__device__ float g_colsum[NUM_ITERS + 1][C];    // per-iteration column sums
__device__ uint4 g_E[(size_t)MAXN * (C / 8)];   // E = exp(S) fp16, 8 halves/uint4

// ---------------------------------------------------------------------------
__global__ void init_k(const float* __restrict__ ratios,
                       const int* __restrict__ total_num) {
    int j = threadIdx.x;
    float tn = (float)(*total_num);
    g_b[j] = ratios[j] * tn;
    #pragma unroll
    for (int t = 0; t <= NUM_ITERS; ++t) g_colsum[t][j] = 0.0f;
}

// ---------------------------------------------------------------------------
// Pass 1 (iteration 1, v0=1), fused with E=exp(S) fp16 store. Unroll x2.
// One warp per row; lane owns 4 cols (float4).
// ---------------------------------------------------------------------------
__global__ void __launch_bounds__(256)
pass1_k(const float4* __restrict__ S4, int N) {
    const int lane = threadIdx.x & 31;
    const int gwarp = blockIdx.x * (blockDim.x >> 5) + (threadIdx.x >> 5);
    const int nwarps = gridDim.x * (blockDim.x >> 5);

    float c0 = 0.f, c1 = 0.f, c2 = 0.f, c3 = 0.f;
    uint2* __restrict__ E2 = reinterpret_cast<uint2*>(g_E);

    int row = gwarp;
    for (; row + nwarps < N; row += 2 * nwarps) {
        float4 sA = S4[(size_t)row * 32 + lane];
        float4 sB = S4[(size_t)(row + nwarps) * 32 + lane];
        float a0 = __expf(sA.x), a1 = __expf(sA.y), a2 = __expf(sA.z), a3 = __expf(sA.w);
        float b0 = __expf(sB.x), b1 = __expf(sB.y), b2 = __expf(sB.z), b3 = __expf(sB.w);

        __half2 hA01 = __floats2half2_rn(a0, a1), hA23 = __floats2half2_rn(a2, a3);
        __half2 hB01 = __floats2half2_rn(b0, b1), hB23 = __floats2half2_rn(b2, b3);
        uint2 pkA, pkB;
        pkA.x = *reinterpret_cast<unsigned*>(&hA01);
        pkA.y = *reinterpret_cast<unsigned*>(&hA23);
        pkB.x = *reinterpret_cast<unsigned*>(&hB01);
        pkB.y = *reinterpret_cast<unsigned*>(&hB23);
        E2[(size_t)row * 32 + lane] = pkA;
        E2[(size_t)(row + nwarps) * 32 + lane] = pkB;

        float pA = (a0 + a1) + (a2 + a3);
        float pB = (b0 + b1) + (b2 + b3);
        #pragma unroll
        for (int o = 16; o; o >>= 1) {
            pA += __shfl_xor_sync(0xffffffffu, pA, o);
            pB += __shfl_xor_sync(0xffffffffu, pB, o);
        }
        float uA = 1.0f / pA, uB = 1.0f / pB;
        c0 = fmaf(uA, a0, fmaf(uB, b0, c0));
        c1 = fmaf(uA, a1, fmaf(uB, b1, c1));
        c2 = fmaf(uA, a2, fmaf(uB, b2, c2));
        c3 = fmaf(uA, a3, fmaf(uB, b3, c3));
    }
    for (; row < N; row += nwarps) {
        float4 s = S4[(size_t)row * 32 + lane];
        float e0 = __expf(s.x), e1 = __expf(s.y), e2 = __expf(s.z), e3 = __expf(s.w);
        __half2 h01 = __floats2half2_rn(e0, e1), h23 = __floats2half2_rn(e2, e3);
        uint2 pk;
        pk.x = *reinterpret_cast<unsigned*>(&h01);
        pk.y = *reinterpret_cast<unsigned*>(&h23);
        E2[(size_t)row * 32 + lane] = pk;
        float p = (e0 + e1) + (e2 + e3);
        #pragma unroll
        for (int o = 16; o; o >>= 1) p += __shfl_xor_sync(0xffffffffu, p, o);
        float u = 1.0f / p;
        c0 = fmaf(u, e0, c0); c1 = fmaf(u, e1, c1);
        c2 = fmaf(u, e2, c2); c3 = fmaf(u, e3, c3);
    }

    __shared__ float scol[C];
    if (threadIdx.x < C) scol[threadIdx.x] = 0.0f;
    __syncthreads();
    int col = lane * 4;
    atomicAdd(&scol[col + 0], c0);
    atomicAdd(&scol[col + 1], c1);
    atomicAdd(&scol[col + 2], c2);
    atomicAdd(&scol[col + 3], c3);
    __syncthreads();
    if (threadIdx.x < C)
        atomicAdd(&g_colsum[1][threadIdx.x], scol[threadIdx.x]);
}

// ---------------------------------------------------------------------------
// Iterations 2..10: fp16 E only. v computed per-block from previous colsum
// (no separate vnorm launch). 16 lanes/row, unroll x4 for MLP.
// ---------------------------------------------------------------------------
__global__ void __launch_bounds__(256)
iterh_k(int NP2, int t) {
    const int lane = threadIdx.x & 31;
    const int sub = lane & 15;
    const int gwarp = blockIdx.x * (blockDim.x >> 5) + (threadIdx.x >> 5);
    const int nwarps = gridDim.x * (blockDim.x >> 5);

    __shared__ float sv[C];
    __shared__ float scol[C];
    if (threadIdx.x < C) {
        sv[threadIdx.x] = g_b[threadIdx.x] / g_colsum[t - 1][threadIdx.x];
        scol[threadIdx.x] = 0.0f;
    }
    __syncthreads();

    float v[8];
    #pragma unroll
    for (int k = 0; k < 8; ++k) v[k] = sv[sub * 8 + k];

    float c[8];
    #pragma unroll
    for (int k = 0; k < 8; ++k) c[k] = 0.0f;

    const uint4* __restrict__ E = g_E;
    int i = gwarp;

    for (; i + 3 * nwarps < NP2; i += 4 * nwarps) {
        uint4 q0 = E[(size_t)i * 32 + lane];
        uint4 q1 = E[(size_t)(i + nwarps) * 32 + lane];
        uint4 q2 = E[(size_t)(i + 2 * nwarps) * 32 + lane];
        uint4 q3 = E[(size_t)(i + 3 * nwarps) * 32 + lane];

        float f[4][8];
        uint4 qq[4] = {q0, q1, q2, q3};
        #pragma unroll
        for (int m = 0; m < 4; ++m) {
            float2 g0 = __half22float2(*reinterpret_cast<__half2*>(&qq[m].x));
            float2 g1 = __half22float2(*reinterpret_cast<__half2*>(&qq[m].y));
            float2 g2 = __half22float2(*reinterpret_cast<__half2*>(&qq[m].z));
            float2 g3 = __half22float2(*reinterpret_cast<__half2*>(&qq[m].w));
            f[m][0] = g0.x; f[m][1] = g0.y; f[m][2] = g1.x; f[m][3] = g1.y;
            f[m][4] = g2.x; f[m][5] = g2.y; f[m][6] = g3.x; f[m][7] = g3.y;
        }

        float p[4];
        #pragma unroll
        for (int m = 0; m < 4; ++m) {
            float t0 = fmaf(f[m][0], v[0], f[m][1] * v[1]);
            float t1 = fmaf(f[m][2], v[2], f[m][3] * v[3]);
            float t2 = fmaf(f[m][4], v[4], f[m][5] * v[5]);
            float t3 = fmaf(f[m][6], v[6], f[m][7] * v[7]);
            p[m] = (t0 + t1) + (t2 + t3);
        }
        #pragma unroll
        for (int o = 8; o; o >>= 1) {
            #pragma unroll
            for (int m = 0; m < 4; ++m)
                p[m] += __shfl_xor_sync(0xffffffffu, p[m], o);
        }
        float u[4];
        #pragma unroll
        for (int m = 0; m < 4; ++m) u[m] = 1.0f / p[m];
        #pragma unroll
        for (int k = 0; k < 8; ++k)
            c[k] = fmaf(u[0], f[0][k],
                   fmaf(u[1], f[1][k],
                   fmaf(u[2], f[2][k],
                   fmaf(u[3], f[3][k], c[k]))));
    }

    for (; i < NP2; i += nwarps) {
        uint4 q = E[(size_t)i * 32 + lane];
        float2 g0 = __half22float2(*reinterpret_cast<__half2*>(&q.x));
        float2 g1 = __half22float2(*reinterpret_cast<__half2*>(&q.y));
        float2 g2 = __half22float2(*reinterpret_cast<__half2*>(&q.z));
        float2 g3 = __half22float2(*reinterpret_cast<__half2*>(&q.w));
        float f0 = g0.x, f1 = g0.y, f2 = g1.x, f3 = g1.y;
        float f4 = g2.x, f5 = g2.y, f6 = g3.x, f7 = g3.y;
        float t0 = fmaf(f0, v[0], f1 * v[1]);
        float t1 = fmaf(f2, v[2], f3 * v[3]);
        float t2 = fmaf(f4, v[4], f5 * v[5]);
        float t3 = fmaf(f6, v[6], f7 * v[7]);
        float p = (t0 + t1) + (t2 + t3);
        #pragma unroll
        for (int o = 8; o; o >>= 1) p += __shfl_xor_sync(0xffffffffu, p, o);
        float u = 1.0f / p;
        c[0] = fmaf(u, f0, c[0]); c[1] = fmaf(u, f1, c[1]);
        c[2] = fmaf(u, f2, c[2]); c[3] = fmaf(u, f3, c[3]);
        c[4] = fmaf(u, f4, c[4]); c[5] = fmaf(u, f5, c[5]);
        c[6] = fmaf(u, f6, c[6]); c[7] = fmaf(u, f7, c[7]);
    }

    __syncthreads();   // scol zeroed before use (init above), ensure visible
    int cb = sub * 8;
    #pragma unroll
    for (int k = 0; k < 8; ++k)
        atomicAdd(&scol[cb + k], c[k]);
    __syncthreads();
    if (threadIdx.x < C)
        atomicAdd(&g_colsum[t][threadIdx.x], scol[threadIdx.x]);
}

// ---------------------------------------------------------------------------
// Final: P_ij = u_i * exp(S_ij) * v10[j], u_i = 1/sum_j exp(S_ij)*v9[j].
// v9/v10 computed per block from colsum[9]/colsum[10]. fp32 S. Unroll x2.
// ---------------------------------------------------------------------------
__global__ void __launch_bounds__(256)
final_k(const float4* __restrict__ S4, float4* __restrict__ out, int N) {
    const int lane = threadIdx.x & 31;
    const int gwarp = blockIdx.x * (blockDim.x >> 5) + (threadIdx.x >> 5);
    const int nwarps = gridDim.x * (blockDim.x >> 5);

    __shared__ float sv9[C], sv10[C];
    if (threadIdx.x < C) {
        sv9[threadIdx.x]  = g_b[threadIdx.x] / g_colsum[NUM_ITERS - 1][threadIdx.x];
        sv10[threadIdx.x] = g_b[threadIdx.x] / g_colsum[NUM_ITERS][threadIdx.x];
    }
    __syncthreads();

    float4 v9  = reinterpret_cast<const float4*>(sv9)[lane];
    float4 v10 = reinterpret_cast<const float4*>(sv10)[lane];

    int row = gwarp;
    for (; row + nwarps < N; row += 2 * nwarps) {
        float4 sA = S4[(size_t)row * 32 + lane];
        float4 sB = S4[(size_t)(row + nwarps) * 32 + lane];
        float a0 = __expf(sA.x), a1 = __expf(sA.y), a2 = __expf(sA.z), a3 = __expf(sA.w);
        float b0 = __expf(sB.x), b1 = __expf(sB.y), b2 = __expf(sB.z), b3 = __expf(sB.w);
        float pA = fmaf(a0, v9.x, fmaf(a1, v9.y, fmaf(a2, v9.z, a3 * v9.w)));
        float pB = fmaf(b0, v9.x, fmaf(b1, v9.y, fmaf(b2, v9.z, b3 * v9.w)));
        #pragma unroll
        for (int o = 16; o; o >>= 1) {
            pA += __shfl_xor_sync(0xffffffffu, pA, o);
            pB += __shfl_xor_sync(0xffffffffu, pB, o);
        }
        float uA = 1.0f / pA, uB = 1.0f / pB;
        float4 oA, oB;
        oA.x = uA * a0 * v10.x; oA.y = uA * a1 * v10.y;
        oA.z = uA * a2 * v10.z; oA.w = uA * a3 * v10.w;
        oB.x = uB * b0 * v10.x; oB.y = uB * b1 * v10.y;
        oB.z = uB * b2 * v10.z; oB.w = uB * b3 * v10.w;
        out[(size_t)row * 32 + lane] = oA;
        out[(size_t)(row + nwarps) * 32 + lane] = oB;
    }
    for (; row < N; row += nwarps) {
        float4 s = S4[(size_t)row * 32 + lane];
        float e0 = __expf(s.x), e1 = __expf(s.y), e2 = __expf(s.z), e3 = __expf(s.w);
        float p = fmaf(e0, v9.x, fmaf(e1, v9.y, fmaf(e2, v9.z, e3 * v9.w)));
        #pragma unroll
        for (int o = 16; o; o >>= 1) p += __shfl_xor_sync(0xffffffffu, p, o);
        float u = 1.0f / p;
        float4 o4;
        o4.x = u * e0 * v10.x; o4.y = u * e1 * v10.y;
        o4.z = u * e2 * v10.z; o4.w = u * e3 * v10.w;
        out[(size_t)row * 32 + lane] = o4;
    }
}

// ---------------------------------------------------------------------------
extern "C" void kernel_launch(void* const* d_in, const int* in_sizes, int n_in,
                              void* d_out, int out_size) {
    const float* S        = (const float*)d_in[2];
    const float* ratios   = (const float*)d_in[3];
    const int*   totalnum = (const int*)d_in[5];
    const int N = in_sizes[2] / C;

    const int GRID = 1184;
    const int BLK  = 256;

    init_k<<<1, C>>>(ratios, totalnum);
    pass1_k<<<GRID, BLK>>>((const float4*)S, N);          // iteration 1
    for (int t = 2; t <= NUM_ITERS; ++t)
        iterh_k<<<GRID, BLK>>>(N / 2, t);                 // iterations 2..10
    final_k<<<GRID, BLK>>>((const float4*)S, (float4*)d_out, N);
}

// round 4
// speedup vs baseline: 1.9131x; 1.4240x over previous
#include <cuda_runtime.h>
#include <cuda_fp16.h>

#define C 128
#define NUM_ITERS 10
#define MAXN 500000

// Scratch (__device__ globals, no allocation).
__device__ float g_b[C];                         // b = ratios * total_num
__device__ float g_colsum[NUM_ITERS + 1][C];     // per-iteration column sums
__device__ uint4 g_E8[(size_t)MAXN * 8];         // E = exp(S) in fp8 e4m3, 128 B/row (64 MB)

// fp8 helpers -----------------------------------------------------------------
__device__ __forceinline__ unsigned short pack_fp8x2(float hi, float lo) {
    unsigned short v;
    asm("cvt.rn.satfinite.e4m3x2.f32 %0, %1, %2;" : "=h"(v) : "f"(hi), "f"(lo));
    return v;   // lo byte = cvt(lo), hi byte = cvt(hi)
}
__device__ __forceinline__ __half2 fp8x2_to_h2(unsigned short p) {
    unsigned r;
    asm("cvt.rn.f16x2.e4m3x2 %0, %1;" : "=r"(r) : "h"(p));
    return *reinterpret_cast<__half2*>(&r);  // .x = cvt(lo byte), .y = cvt(hi byte)
}

// ---------------------------------------------------------------------------
__global__ void init_k(const float* __restrict__ ratios,
                       const int* __restrict__ total_num) {
    int j = threadIdx.x;
    float tn = (float)(*total_num);
    g_b[j] = ratios[j] * tn;
    #pragma unroll
    for (int t = 0; t <= NUM_ITERS; ++t) g_colsum[t][j] = 0.0f;
}

// ---------------------------------------------------------------------------
// Pass 1 (iteration 1, v0=1) fused with E = exp(S) -> fp8 store. Unroll x2.
// One warp per row; lane owns cols 4l..4l+3 (float4 read, 4-byte fp8 write).
// ---------------------------------------------------------------------------
__global__ void __launch_bounds__(256)
pass1_k(const float4* __restrict__ S4, int N) {
    const int lane = threadIdx.x & 31;
    const int gwarp = blockIdx.x * (blockDim.x >> 5) + (threadIdx.x >> 5);
    const int nwarps = gridDim.x * (blockDim.x >> 5);

    float c0 = 0.f, c1 = 0.f, c2 = 0.f, c3 = 0.f;
    unsigned* __restrict__ E8 = reinterpret_cast<unsigned*>(g_E8);

    int row = gwarp;
    for (; row + nwarps < N; row += 2 * nwarps) {
        float4 sA = S4[(size_t)row * 32 + lane];
        float4 sB = S4[(size_t)(row + nwarps) * 32 + lane];
        float a0 = __expf(sA.x), a1 = __expf(sA.y), a2 = __expf(sA.z), a3 = __expf(sA.w);
        float b0 = __expf(sB.x), b1 = __expf(sB.y), b2 = __expf(sB.z), b3 = __expf(sB.w);

        unsigned pkA = (unsigned)pack_fp8x2(a1, a0) | ((unsigned)pack_fp8x2(a3, a2) << 16);
        unsigned pkB = (unsigned)pack_fp8x2(b1, b0) | ((unsigned)pack_fp8x2(b3, b2) << 16);
        E8[(size_t)row * 32 + lane] = pkA;
        E8[(size_t)(row + nwarps) * 32 + lane] = pkB;

        float pA = (a0 + a1) + (a2 + a3);
        float pB = (b0 + b1) + (b2 + b3);
        #pragma unroll
        for (int o = 16; o; o >>= 1) {
            pA += __shfl_xor_sync(0xffffffffu, pA, o);
            pB += __shfl_xor_sync(0xffffffffu, pB, o);
        }
        float uA = 1.0f / pA, uB = 1.0f / pB;
        c0 = fmaf(uA, a0, fmaf(uB, b0, c0));
        c1 = fmaf(uA, a1, fmaf(uB, b1, c1));
        c2 = fmaf(uA, a2, fmaf(uB, b2, c2));
        c3 = fmaf(uA, a3, fmaf(uB, b3, c3));
    }
    for (; row < N; row += nwarps) {
        float4 s = S4[(size_t)row * 32 + lane];
        float e0 = __expf(s.x), e1 = __expf(s.y), e2 = __expf(s.z), e3 = __expf(s.w);
        unsigned pk = (unsigned)pack_fp8x2(e1, e0) | ((unsigned)pack_fp8x2(e3, e2) << 16);
        E8[(size_t)row * 32 + lane] = pk;
        float p = (e0 + e1) + (e2 + e3);
        #pragma unroll
        for (int o = 16; o; o >>= 1) p += __shfl_xor_sync(0xffffffffu, p, o);
        float u = 1.0f / p;
        c0 = fmaf(u, e0, c0); c1 = fmaf(u, e1, c1);
        c2 = fmaf(u, e2, c2); c3 = fmaf(u, e3, c3);
    }

    __shared__ float scol[C];
    if (threadIdx.x < C) scol[threadIdx.x] = 0.0f;
    __syncthreads();
    int col = lane * 4;
    atomicAdd(&scol[col + 0], c0);
    atomicAdd(&scol[col + 1], c1);
    atomicAdd(&scol[col + 2], c2);
    atomicAdd(&scol[col + 3], c3);
    __syncthreads();
    if (threadIdx.x < C)
        atomicAdd(&g_colsum[1][threadIdx.x], scol[threadIdx.x]);
}

// ---------------------------------------------------------------------------
// Iterations 2..10 on fp8 E, half2 math.
// Row = 128 B fp8; 8 lanes/row (16 cols each via one uint4); warp = 4 rows
// per load; 4 loads in flight per loop. v from previous colsum (no vnorm).
// ---------------------------------------------------------------------------
__global__ void __launch_bounds__(256)
iter8_k(int N, int t) {
    const int lane = threadIdx.x & 31;
    const int sub = lane & 7;            // 16-col slice within row
    const int gwarp = blockIdx.x * (blockDim.x >> 5) + (threadIdx.x >> 5);
    const int nwarps = gridDim.x * (blockDim.x >> 5);

    __shared__ float sv[C];
    __shared__ float scol[C];
    if (threadIdx.x < C) {
        sv[threadIdx.x] = g_b[threadIdx.x] / g_colsum[t - 1][threadIdx.x];
        scol[threadIdx.x] = 0.0f;
    }
    __syncthreads();

    __half2 v2[8];
    #pragma unroll
    for (int k = 0; k < 8; ++k)
        v2[k] = __floats2half2_rn(sv[sub * 16 + 2 * k], sv[sub * 16 + 2 * k + 1]);

    __half2 c2[8];
    #pragma unroll
    for (int k = 0; k < 8; ++k) c2[k] = __floats2half2_rn(0.f, 0.f);

    const uint4* __restrict__ E = g_E8;
    const int G = N >> 2;                // groups of 4 rows

    // per-group processing (q -> row contribution)
    auto process = [&](uint4 q) {
        __half2 h[8];
        h[0] = fp8x2_to_h2((unsigned short)(q.x & 0xffff));
        h[1] = fp8x2_to_h2((unsigned short)(q.x >> 16));
        h[2] = fp8x2_to_h2((unsigned short)(q.y & 0xffff));
        h[3] = fp8x2_to_h2((unsigned short)(q.y >> 16));
        h[4] = fp8x2_to_h2((unsigned short)(q.z & 0xffff));
        h[5] = fp8x2_to_h2((unsigned short)(q.z >> 16));
        h[6] = fp8x2_to_h2((unsigned short)(q.w & 0xffff));
        h[7] = fp8x2_to_h2((unsigned short)(q.w >> 16));
        __half2 pa = __hmul2(h[0], v2[0]);
        __half2 pb = __hmul2(h[4], v2[4]);
        pa = __hfma2(h[1], v2[1], pa);
        pb = __hfma2(h[5], v2[5], pb);
        pa = __hfma2(h[2], v2[2], pa);
        pb = __hfma2(h[6], v2[6], pb);
        pa = __hfma2(h[3], v2[3], pa);
        pb = __hfma2(h[7], v2[7], pb);
        pa = __hadd2(pa, pb);
        float2 pf = __half22float2(pa);
        float p = pf.x + pf.y;
        p += __shfl_xor_sync(0xffffffffu, p, 4);
        p += __shfl_xor_sync(0xffffffffu, p, 2);
        p += __shfl_xor_sync(0xffffffffu, p, 1);
        __half2 u2 = __float2half2_rn(1.0f / p);
        #pragma unroll
        for (int k = 0; k < 8; ++k)
            c2[k] = __hfma2(u2, h[k], c2[k]);
    };

    int g = gwarp;
    for (; g + 3 * nwarps < G; g += 4 * nwarps) {
        uint4 q0 = E[(size_t)g * 32 + lane];
        uint4 q1 = E[(size_t)(g + nwarps) * 32 + lane];
        uint4 q2 = E[(size_t)(g + 2 * nwarps) * 32 + lane];
        uint4 q3 = E[(size_t)(g + 3 * nwarps) * 32 + lane];
        process(q0);
        process(q1);
        process(q2);
        process(q3);
    }
    for (; g < G; g += nwarps)
        process(E[(size_t)g * 32 + lane]);

    // Remainder rows (N % 4) — rare path, one warp per row, lanes 0-7 only.
    int rem = N & 3;
    if (gwarp < rem && lane < 8) {
        int row = G * 4 + gwarp;
        uint4 q = E[(size_t)row * 8 + sub];  // 8 uint4 per row
        __half2 h[8];
        h[0] = fp8x2_to_h2((unsigned short)(q.x & 0xffff));
        h[1] = fp8x2_to_h2((unsigned short)(q.x >> 16));
        h[2] = fp8x2_to_h2((unsigned short)(q.y & 0xffff));
        h[3] = fp8x2_to_h2((unsigned short)(q.y >> 16));
        h[4] = fp8x2_to_h2((unsigned short)(q.z & 0xffff));
        h[5] = fp8x2_to_h2((unsigned short)(q.z >> 16));
        h[6] = fp8x2_to_h2((unsigned short)(q.w & 0xffff));
        h[7] = fp8x2_to_h2((unsigned short)(q.w >> 16));
        float p = 0.f;
        #pragma unroll
        for (int k = 0; k < 8; ++k) {
            float2 pr = __half22float2(__hmul2(h[k], v2[k]));
            p += pr.x + pr.y;
        }
        p += __shfl_xor_sync(0x000000ffu, p, 4);
        p += __shfl_xor_sync(0x000000ffu, p, 2);
        p += __shfl_xor_sync(0x000000ffu, p, 1);
        __half2 u2 = __float2half2_rn(1.0f / p);
        #pragma unroll
        for (int k = 0; k < 8; ++k)
            c2[k] = __hfma2(u2, h[k], c2[k]);
    }

    // Warp-reduce c2 across the 4 row-slots (lanes l, l+8, l+16, l+24).
    #pragma unroll
    for (int k = 0; k < 8; ++k) {
        unsigned pk = *reinterpret_cast<unsigned*>(&c2[k]);
        unsigned o1 = __shfl_xor_sync(0xffffffffu, pk, 8);
        __half2 s = __hadd2(c2[k], *reinterpret_cast<__half2*>(&o1));
        unsigned ps = *reinterpret_cast<unsigned*>(&s);
        unsigned o2 = __shfl_xor_sync(0xffffffffu, ps, 16);
        s = __hadd2(s, *reinterpret_cast<__half2*>(&o2));
        c2[k] = s;
    }
    if (lane < 8) {
        #pragma unroll
        for (int k = 0; k < 8; ++k) {
            float2 cf = __half22float2(c2[k]);
            atomicAdd(&scol[sub * 16 + 2 * k], cf.x);
            atomicAdd(&scol[sub * 16 + 2 * k + 1], cf.y);
        }
    }
    __syncthreads();
    if (threadIdx.x < C)
        atomicAdd(&g_colsum[t][threadIdx.x], scol[threadIdx.x]);
}

// ---------------------------------------------------------------------------
// Final: P_ij = u_i * exp(S_ij) * v10[j], u_i = 1/sum_j exp(S_ij)*v9[j].
// fp32 S for output precision. Unroll x2.
// ---------------------------------------------------------------------------
__global__ void __launch_bounds__(256)
final_k(const float4* __restrict__ S4, float4* __restrict__ out, int N) {
    const int lane = threadIdx.x & 31;
    const int gwarp = blockIdx.x * (blockDim.x >> 5) + (threadIdx.x >> 5);
    const int nwarps = gridDim.x * (blockDim.x >> 5);

    __shared__ float sv9[C], sv10[C];
    if (threadIdx.x < C) {
        sv9[threadIdx.x]  = g_b[threadIdx.x] / g_colsum[NUM_ITERS - 1][threadIdx.x];
        sv10[threadIdx.x] = g_b[threadIdx.x] / g_colsum[NUM_ITERS][threadIdx.x];
    }
    __syncthreads();

    float4 v9  = reinterpret_cast<const float4*>(sv9)[lane];
    float4 v10 = reinterpret_cast<const float4*>(sv10)[lane];

    int row = gwarp;
    for (; row + nwarps < N; row += 2 * nwarps) {
        float4 sA = S4[(size_t)row * 32 + lane];
        float4 sB = S4[(size_t)(row + nwarps) * 32 + lane];
        float a0 = __expf(sA.x), a1 = __expf(sA.y), a2 = __expf(sA.z), a3 = __expf(sA.w);
        float b0 = __expf(sB.x), b1 = __expf(sB.y), b2 = __expf(sB.z), b3 = __expf(sB.w);
        float pA = fmaf(a0, v9.x, fmaf(a1, v9.y, fmaf(a2, v9.z, a3 * v9.w)));
        float pB = fmaf(b0, v9.x, fmaf(b1, v9.y, fmaf(b2, v9.z, b3 * v9.w)));
        #pragma unroll
        for (int o = 16; o; o >>= 1) {
            pA += __shfl_xor_sync(0xffffffffu, pA, o);
            pB += __shfl_xor_sync(0xffffffffu, pB, o);
        }
        float uA = 1.0f / pA, uB = 1.0f / pB;
        float4 oA, oB;
        oA.x = uA * a0 * v10.x; oA.y = uA * a1 * v10.y;
        oA.z = uA * a2 * v10.z; oA.w = uA * a3 * v10.w;
        oB.x = uB * b0 * v10.x; oB.y = uB * b1 * v10.y;
        oB.z = uB * b2 * v10.z; oB.w = uB * b3 * v10.w;
        out[(size_t)row * 32 + lane] = oA;
        out[(size_t)(row + nwarps) * 32 + lane] = oB;
    }
    for (; row < N; row += nwarps) {
        float4 s = S4[(size_t)row * 32 + lane];
        float e0 = __expf(s.x), e1 = __expf(s.y), e2 = __expf(s.z), e3 = __expf(s.w);
        float p = fmaf(e0, v9.x, fmaf(e1, v9.y, fmaf(e2, v9.z, e3 * v9.w)));
        #pragma unroll
        for (int o = 16; o; o >>= 1) p += __shfl_xor_sync(0xffffffffu, p, o);
        float u = 1.0f / p;
        float4 o4;
        o4.x = u * e0 * v10.x; o4.y = u * e1 * v10.y;
        o4.z = u * e2 * v10.z; o4.w = u * e3 * v10.w;
        out[(size_t)row * 32 + lane] = o4;
    }
}

// ---------------------------------------------------------------------------
extern "C" void kernel_launch(void* const* d_in, const int* in_sizes, int n_in,
                              void* d_out, int out_size) {
    const float* S        = (const float*)d_in[2];
    const float* ratios   = (const float*)d_in[3];
    const int*   totalnum = (const int*)d_in[5];
    const int N = in_sizes[2] / C;

    const int GRID = 1184;
    const int BLK  = 256;

    init_k<<<1, C>>>(ratios, totalnum);
    pass1_k<<<GRID, BLK>>>((const float4*)S, N);          // iteration 1 + E8 store
    for (int t = 2; t <= NUM_ITERS; ++t)
        iter8_k<<<GRID, BLK>>>(N, t);                     // iterations 2..10 (fp8)
    final_k<<<GRID, BLK>>>((const float4*)S, (float4*)d_out, N);
}

// round 6
// speedup vs baseline: 2.0947x; 1.0950x over previous
#include <cuda_runtime.h>
#include <cuda_fp16.h>

#define C 128
#define NUM_ITERS 10
#define MAXN 500000
#define PGRID 296          // 2 blocks/SM * 148 SMs: guaranteed co-resident
#define PBLK  256

// Scratch (__device__ globals, no allocation).
__device__ float g_b[C];                         // b = ratios * total_num
__device__ float g_colsum[NUM_ITERS + 1][C];     // per-iteration column sums
__device__ int   g_arrive;                       // monotonic grid-barrier counter
__device__ uint4 g_E8[(size_t)MAXN * 8];         // E = exp(S) fp8 e4m3, 128 B/row

// ---- fp8 helpers -------------------------------------------------------------
__device__ __forceinline__ unsigned short pack_fp8x2(float hi, float lo) {
    unsigned short v;
    asm("cvt.rn.satfinite.e4m3x2.f32 %0, %1, %2;" : "=h"(v) : "f"(hi), "f"(lo));
    return v;
}
__device__ __forceinline__ __half2 fp8x2_to_h2(unsigned short p) {
    unsigned r;
    asm("cvt.rn.f16x2.e4m3x2 %0, %1;" : "=r"(r) : "h"(p));
    return *reinterpret_cast<__half2*>(&r);
}

// ---- cache-policy helpers (createpolicy + cache_hint forms) -------------------
__device__ __forceinline__ unsigned long long pol_evict_last() {
    unsigned long long p;
    asm("createpolicy.fractional.L2::evict_last.b64 %0, 1.0;" : "=l"(p));
    return p;
}
__device__ __forceinline__ unsigned long long pol_evict_first() {
    unsigned long long p;
    asm("createpolicy.fractional.L2::evict_first.b64 %0, 1.0;" : "=l"(p));
    return p;
}
__device__ __forceinline__ uint4 ldg_hint_u4(const uint4* p, unsigned long long pol) {
    uint4 q;
    asm volatile("ld.global.nc.L2::cache_hint.v4.u32 {%0,%1,%2,%3}, [%4], %5;"
                 : "=r"(q.x), "=r"(q.y), "=r"(q.z), "=r"(q.w) : "l"(p), "l"(pol));
    return q;
}
__device__ __forceinline__ float4 ldg_hint_f4(const float4* p, unsigned long long pol) {
    float4 q;
    asm volatile("ld.global.nc.L2::cache_hint.v4.f32 {%0,%1,%2,%3}, [%4], %5;"
                 : "=f"(q.x), "=f"(q.y), "=f"(q.z), "=f"(q.w) : "l"(p), "l"(pol));
    return q;
}
__device__ __forceinline__ void stg_hint_u32(unsigned* p, unsigned v, unsigned long long pol) {
    asm volatile("st.global.L2::cache_hint.u32 [%0], %1, %2;"
                 :: "l"(p), "r"(v), "l"(pol) : "memory");
}

// ---------------------------------------------------------------------------
__global__ void init_k(const float* __restrict__ ratios,
                       const int* __restrict__ total_num) {
    int j = threadIdx.x;
    float tn = (float)(*total_num);
    g_b[j] = ratios[j] * tn;
    #pragma unroll
    for (int t = 0; t <= NUM_ITERS; ++t) g_colsum[t][j] = 0.0f;
    if (j == 0) g_arrive = 0;
}

// ---------------------------------------------------------------------------
// Pass 1 (iteration 1, v0=1) fused with E = exp(S) -> fp8 store. Unroll x4.
// S reads evict_first (protect E8 L2 residency); E8 stores evict_last.
// ---------------------------------------------------------------------------
__global__ void __launch_bounds__(256)
pass1_k(const float4* __restrict__ S4, int N) {
    const int lane = threadIdx.x & 31;
    const int gwarp = blockIdx.x * (blockDim.x >> 5) + (threadIdx.x >> 5);
    const int nwarps = gridDim.x * (blockDim.x >> 5);
    const unsigned long long pol_ef = pol_evict_first();
    const unsigned long long pol_el = pol_evict_last();

    float c0 = 0.f, c1 = 0.f, c2 = 0.f, c3 = 0.f;
    unsigned* __restrict__ E8 = reinterpret_cast<unsigned*>(g_E8);

    int row = gwarp;
    for (; row + 3 * nwarps < N; row += 4 * nwarps) {
        float4 s[4];
        #pragma unroll
        for (int m = 0; m < 4; ++m)
            s[m] = ldg_hint_f4(&S4[(size_t)(row + m * nwarps) * 32 + lane], pol_ef);

        float e[4][4], p[4];
        #pragma unroll
        for (int m = 0; m < 4; ++m) {
            e[m][0] = __expf(s[m].x); e[m][1] = __expf(s[m].y);
            e[m][2] = __expf(s[m].z); e[m][3] = __expf(s[m].w);
            unsigned pk = (unsigned)pack_fp8x2(e[m][1], e[m][0])
                        | ((unsigned)pack_fp8x2(e[m][3], e[m][2]) << 16);
            stg_hint_u32(&E8[(size_t)(row + m * nwarps) * 32 + lane], pk, pol_el);
            p[m] = (e[m][0] + e[m][1]) + (e[m][2] + e[m][3]);
        }
        #pragma unroll
        for (int o = 16; o; o >>= 1) {
            #pragma unroll
            for (int m = 0; m < 4; ++m)
                p[m] += __shfl_xor_sync(0xffffffffu, p[m], o);
        }
        #pragma unroll
        for (int m = 0; m < 4; ++m) {
            float u = 1.0f / p[m];
            c0 = fmaf(u, e[m][0], c0); c1 = fmaf(u, e[m][1], c1);
            c2 = fmaf(u, e[m][2], c2); c3 = fmaf(u, e[m][3], c3);
        }
    }
    for (; row < N; row += nwarps) {
        float4 s = ldg_hint_f4(&S4[(size_t)row * 32 + lane], pol_ef);
        float e0 = __expf(s.x), e1 = __expf(s.y), e2 = __expf(s.z), e3 = __expf(s.w);
        unsigned pk = (unsigned)pack_fp8x2(e1, e0) | ((unsigned)pack_fp8x2(e3, e2) << 16);
        stg_hint_u32(&E8[(size_t)row * 32 + lane], pk, pol_el);
        float p = (e0 + e1) + (e2 + e3);
        #pragma unroll
        for (int o = 16; o; o >>= 1) p += __shfl_xor_sync(0xffffffffu, p, o);
        float u = 1.0f / p;
        c0 = fmaf(u, e0, c0); c1 = fmaf(u, e1, c1);
        c2 = fmaf(u, e2, c2); c3 = fmaf(u, e3, c3);
    }

    __shared__ float scol[C];
    if (threadIdx.x < C) scol[threadIdx.x] = 0.0f;
    __syncthreads();
    int col = lane * 4;
    atomicAdd(&scol[col + 0], c0);
    atomicAdd(&scol[col + 1], c1);
    atomicAdd(&scol[col + 2], c2);
    atomicAdd(&scol[col + 3], c3);
    __syncthreads();
    if (threadIdx.x < C)
        atomicAdd(&g_colsum[1][threadIdx.x], scol[threadIdx.x]);
}

// ---------------------------------------------------------------------------
// Persistent kernel: iterations 2..10 on fp8 E with software grid barriers.
// 296 blocks x 256 threads, guaranteed co-resident (launch_bounds(256,2)).
// ---------------------------------------------------------------------------
__global__ void __launch_bounds__(PBLK, 2)
sinkiters_k(int N) {
    const int lane = threadIdx.x & 31;
    const int sub = lane & 7;
    const int gwarp = blockIdx.x * (PBLK >> 5) + (threadIdx.x >> 5);
    const int nwarps = PGRID * (PBLK >> 5);
    const int G = N >> 2;
    const int rem = N & 3;
    const unsigned long long pol_el = pol_evict_last();

    __shared__ float sv[C];
    __shared__ float scol[C];

    for (int t = 2; t <= NUM_ITERS; ++t) {
        if (threadIdx.x < C) {
            sv[threadIdx.x] = g_b[threadIdx.x] / __ldcg(&g_colsum[t - 1][threadIdx.x]);
            scol[threadIdx.x] = 0.0f;
        }
        __syncthreads();

        __half2 v2[8], c2[8];
        #pragma unroll
        for (int k = 0; k < 8; ++k) {
            v2[k] = __floats2half2_rn(sv[sub * 16 + 2 * k], sv[sub * 16 + 2 * k + 1]);
            c2[k] = __floats2half2_rn(0.f, 0.f);
        }

        auto process = [&](uint4 q) {
            __half2 h[8];
            h[0] = fp8x2_to_h2((unsigned short)(q.x & 0xffff));
            h[1] = fp8x2_to_h2((unsigned short)(q.x >> 16));
            h[2] = fp8x2_to_h2((unsigned short)(q.y & 0xffff));
            h[3] = fp8x2_to_h2((unsigned short)(q.y >> 16));
            h[4] = fp8x2_to_h2((unsigned short)(q.z & 0xffff));
            h[5] = fp8x2_to_h2((unsigned short)(q.z >> 16));
            h[6] = fp8x2_to_h2((unsigned short)(q.w & 0xffff));
            h[7] = fp8x2_to_h2((unsigned short)(q.w >> 16));
            __half2 pa = __hmul2(h[0], v2[0]);
            __half2 pb = __hmul2(h[4], v2[4]);
            pa = __hfma2(h[1], v2[1], pa);
            pb = __hfma2(h[5], v2[5], pb);
            pa = __hfma2(h[2], v2[2], pa);
            pb = __hfma2(h[6], v2[6], pb);
            pa = __hfma2(h[3], v2[3], pa);
            pb = __hfma2(h[7], v2[7], pb);
            pa = __hadd2(pa, pb);
            float2 pf = __half22float2(pa);
            float p = pf.x + pf.y;
            p += __shfl_xor_sync(0xffffffffu, p, 4);
            p += __shfl_xor_sync(0xffffffffu, p, 2);
            p += __shfl_xor_sync(0xffffffffu, p, 1);
            __half2 u2 = __float2half2_rn(1.0f / p);
            #pragma unroll
            for (int k = 0; k < 8; ++k)
                c2[k] = __hfma2(u2, h[k], c2[k]);
        };

        int g = gwarp;
        for (; g + 3 * nwarps < G; g += 4 * nwarps) {
            uint4 q0 = ldg_hint_u4(&g_E8[(size_t)g * 32 + lane], pol_el);
            uint4 q1 = ldg_hint_u4(&g_E8[(size_t)(g + nwarps) * 32 + lane], pol_el);
            uint4 q2 = ldg_hint_u4(&g_E8[(size_t)(g + 2 * nwarps) * 32 + lane], pol_el);
            uint4 q3 = ldg_hint_u4(&g_E8[(size_t)(g + 3 * nwarps) * 32 + lane], pol_el);
            process(q0); process(q1); process(q2); process(q3);
        }
        for (; g < G; g += nwarps)
            process(ldg_hint_u4(&g_E8[(size_t)g * 32 + lane], pol_el));

        if (gwarp < rem && lane < 8) {   // remainder rows (N % 4)
            int row = G * 4 + gwarp;
            uint4 q = g_E8[(size_t)row * 8 + sub];
            __half2 h[8];
            h[0] = fp8x2_to_h2((unsigned short)(q.x & 0xffff));
            h[1] = fp8x2_to_h2((unsigned short)(q.x >> 16));
            h[2] = fp8x2_to_h2((unsigned short)(q.y & 0xffff));
            h[3] = fp8x2_to_h2((unsigned short)(q.y >> 16));
            h[4] = fp8x2_to_h2((unsigned short)(q.z & 0xffff));
            h[5] = fp8x2_to_h2((unsigned short)(q.z >> 16));
            h[6] = fp8x2_to_h2((unsigned short)(q.w & 0xffff));
            h[7] = fp8x2_to_h2((unsigned short)(q.w >> 16));
            float p = 0.f;
            #pragma unroll
            for (int k = 0; k < 8; ++k) {
                float2 pr = __half22float2(__hmul2(h[k], v2[k]));
                p += pr.x + pr.y;
            }
            p += __shfl_xor_sync(0x000000ffu, p, 4);
            p += __shfl_xor_sync(0x000000ffu, p, 2);
            p += __shfl_xor_sync(0x000000ffu, p, 1);
            __half2 u2 = __float2half2_rn(1.0f / p);
            #pragma unroll
            for (int k = 0; k < 8; ++k)
                c2[k] = __hfma2(u2, h[k], c2[k]);
        }

        // Reduce c2 across the 4 row-slots of the warp (lanes l, l+8, l+16, l+24).
        #pragma unroll
        for (int k = 0; k < 8; ++k) {
            unsigned pk = *reinterpret_cast<unsigned*>(&c2[k]);
            unsigned o1 = __shfl_xor_sync(0xffffffffu, pk, 8);
            __half2 s = __hadd2(c2[k], *reinterpret_cast<__half2*>(&o1));
            unsigned ps = *reinterpret_cast<unsigned*>(&s);
            unsigned o2 = __shfl_xor_sync(0xffffffffu, ps, 16);
            c2[k] = __hadd2(s, *reinterpret_cast<__half2*>(&o2));
        }
        if (lane < 8) {
            #pragma unroll
            for (int k = 0; k < 8; ++k) {
                float2 cf = __half22float2(c2[k]);
                atomicAdd(&scol[sub * 16 + 2 * k], cf.x);
                atomicAdd(&scol[sub * 16 + 2 * k + 1], cf.y);
            }
        }
        __syncthreads();
        if (threadIdx.x < C)
            atomicAdd(&g_colsum[t][threadIdx.x], scol[threadIdx.x]);

        // Grid barrier (skip after the last iteration).
        if (t < NUM_ITERS) {
            __threadfence();          // publish this block's colsum atomics
            __syncthreads();
            if (threadIdx.x == 0) {
                atomicAdd(&g_arrive, 1);
                const int target = (t - 1) * PGRID;
                int cur;
                do {
                    asm volatile("ld.global.cg.s32 %0, [%1];" : "=r"(cur) : "l"(&g_arrive));
                    if (cur < target) __nanosleep(128);
                } while (cur < target);
                __threadfence();
            }
            __syncthreads();
        }
    }
}

// ---------------------------------------------------------------------------
// Final: P_ij = u_i * exp(S_ij) * v10[j], u_i = 1/sum_j exp(S_ij)*v9[j].
// fp32 S for output precision. Unroll x2.
// ---------------------------------------------------------------------------
__global__ void __launch_bounds__(256)
final_k(const float4* __restrict__ S4, float4* __restrict__ out, int N) {
    const int lane = threadIdx.x & 31;
    const int gwarp = blockIdx.x * (blockDim.x >> 5) + (threadIdx.x >> 5);
    const int nwarps = gridDim.x * (blockDim.x >> 5);

    __shared__ float sv9[C], sv10[C];
    if (threadIdx.x < C) {
        sv9[threadIdx.x]  = g_b[threadIdx.x] / __ldcg(&g_colsum[NUM_ITERS - 1][threadIdx.x]);
        sv10[threadIdx.x] = g_b[threadIdx.x] / __ldcg(&g_colsum[NUM_ITERS][threadIdx.x]);
    }
    __syncthreads();

    float4 v9  = reinterpret_cast<const float4*>(sv9)[lane];
    float4 v10 = reinterpret_cast<const float4*>(sv10)[lane];

    int row = gwarp;
    for (; row + nwarps < N; row += 2 * nwarps) {
        float4 sA = S4[(size_t)row * 32 + lane];
        float4 sB = S4[(size_t)(row + nwarps) * 32 + lane];
        float a0 = __expf(sA.x), a1 = __expf(sA.y), a2 = __expf(sA.z), a3 = __expf(sA.w);
        float b0 = __expf(sB.x), b1 = __expf(sB.y), b2 = __expf(sB.z), b3 = __expf(sB.w);
        float pA = fmaf(a0, v9.x, fmaf(a1, v9.y, fmaf(a2, v9.z, a3 * v9.w)));
        float pB = fmaf(b0, v9.x, fmaf(b1, v9.y, fmaf(b2, v9.z, b3 * v9.w)));
        #pragma unroll
        for (int o = 16; o; o >>= 1) {
            pA += __shfl_xor_sync(0xffffffffu, pA, o);
            pB += __shfl_xor_sync(0xffffffffu, pB, o);
        }
        float uA = 1.0f / pA, uB = 1.0f / pB;
        float4 oA, oB;
        oA.x = uA * a0 * v10.x; oA.y = uA * a1 * v10.y;
        oA.z = uA * a2 * v10.z; oA.w = uA * a3 * v10.w;
        oB.x = uB * b0 * v10.x; oB.y = uB * b1 * v10.y;
        oB.z = uB * b2 * v10.z; oB.w = uB * b3 * v10.w;
        out[(size_t)row * 32 + lane] = oA;
        out[(size_t)(row + nwarps) * 32 + lane] = oB;
    }
    for (; row < N; row += nwarps) {
        float4 s = S4[(size_t)row * 32 + lane];
        float e0 = __expf(s.x), e1 = __expf(s.y), e2 = __expf(s.z), e3 = __expf(s.w);
        float p = fmaf(e0, v9.x, fmaf(e1, v9.y, fmaf(e2, v9.z, e3 * v9.w)));
        #pragma unroll
        for (int o = 16; o; o >>= 1) p += __shfl_xor_sync(0xffffffffu, p, o);
        float u = 1.0f / p;
        float4 o4;
        o4.x = u * e0 * v10.x; o4.y = u * e1 * v10.y;
        o4.z = u * e2 * v10.z; o4.w = u * e3 * v10.w;
        out[(size_t)row * 32 + lane] = o4;
    }
}

// ---------------------------------------------------------------------------
extern "C" void kernel_launch(void* const* d_in, const int* in_sizes, int n_in,
                              void* d_out, int out_size) {
    const float* S        = (const float*)d_in[2];
    const float* ratios   = (const float*)d_in[3];
    const int*   totalnum = (const int*)d_in[5];
    const int N = in_sizes[2] / C;

    init_k<<<1, C>>>(ratios, totalnum);
    pass1_k<<<1184, 256>>>((const float4*)S, N);      // iteration 1 + E8 store
    sinkiters_k<<<PGRID, PBLK>>>(N);                  // iterations 2..10 (persistent)
    final_k<<<1184, 256>>>((const float4*)S, (float4*)d_out, N);
}

// round 7
// speedup vs baseline: 2.1888x; 1.0449x over previous
#include <cuda_runtime.h>
#include <cuda_fp16.h>

#define C 128
#define NUM_ITERS 10
#define MAXN 500000
#define PGRID 592          // 4 blocks/SM * 148 SMs: guaranteed co-resident
#define PBLK  256

// Scratch (__device__ globals, no allocation).
__device__ float g_b[C];                         // b = ratios * total_num
__device__ float g_colsum[NUM_ITERS + 1][C];     // per-iteration column sums
__device__ int   g_arrive;                       // monotonic grid-barrier counter
__device__ uint4 g_E8[(size_t)MAXN * 8];         // E = exp(S) fp8 e4m3, 128 B/row

// ---- fp8 helpers -------------------------------------------------------------
__device__ __forceinline__ unsigned short pack_fp8x2(float hi, float lo) {
    unsigned short v;
    asm("cvt.rn.satfinite.e4m3x2.f32 %0, %1, %2;" : "=h"(v) : "f"(hi), "f"(lo));
    return v;
}
__device__ __forceinline__ __half2 fp8x2_to_h2(unsigned short p) {
    unsigned r;
    asm("cvt.rn.f16x2.e4m3x2 %0, %1;" : "=r"(r) : "h"(p));
    return *reinterpret_cast<__half2*>(&r);
}

// ---- cache-policy helpers (createpolicy + cache_hint forms) -------------------
__device__ __forceinline__ unsigned long long pol_evict_last() {
    unsigned long long p;
    asm("createpolicy.fractional.L2::evict_last.b64 %0, 1.0;" : "=l"(p));
    return p;
}
__device__ __forceinline__ unsigned long long pol_evict_first() {
    unsigned long long p;
    asm("createpolicy.fractional.L2::evict_first.b64 %0, 1.0;" : "=l"(p));
    return p;
}
__device__ __forceinline__ uint4 ldg_hint_u4(const uint4* p, unsigned long long pol) {
    uint4 q;
    asm volatile("ld.global.nc.L2::cache_hint.v4.u32 {%0,%1,%2,%3}, [%4], %5;"
                 : "=r"(q.x), "=r"(q.y), "=r"(q.z), "=r"(q.w) : "l"(p), "l"(pol));
    return q;
}
__device__ __forceinline__ float4 ldg_hint_f4(const float4* p, unsigned long long pol) {
    float4 q;
    asm volatile("ld.global.nc.L2::cache_hint.v4.f32 {%0,%1,%2,%3}, [%4], %5;"
                 : "=f"(q.x), "=f"(q.y), "=f"(q.z), "=f"(q.w) : "l"(p), "l"(pol));
    return q;
}
__device__ __forceinline__ void stg_hint_u32(unsigned* p, unsigned v, unsigned long long pol) {
    asm volatile("st.global.L2::cache_hint.u32 [%0], %1, %2;"
                 :: "l"(p), "r"(v), "l"(pol) : "memory");
}
__device__ __forceinline__ void stg_hint_f4(float4* p, float4 v, unsigned long long pol) {
    asm volatile("st.global.L2::cache_hint.v4.f32 [%0], {%1,%2,%3,%4}, %5;"
                 :: "l"(p), "f"(v.x), "f"(v.y), "f"(v.z), "f"(v.w), "l"(pol) : "memory");
}

// ---------------------------------------------------------------------------
__global__ void init_k(const float* __restrict__ ratios,
                       const int* __restrict__ total_num) {
    int j = threadIdx.x;
    float tn = (float)(*total_num);
    g_b[j] = ratios[j] * tn;
    #pragma unroll
    for (int t = 0; t <= NUM_ITERS; ++t) g_colsum[t][j] = 0.0f;
    if (j == 0) g_arrive = 0;
}

// ---------------------------------------------------------------------------
// Pass 1 (iteration 1, v0=1) fused with E = exp(S) -> fp8 store. Unroll x4.
// S reads evict_first (protect E8 L2 residency); E8 stores evict_last.
// ---------------------------------------------------------------------------
__global__ void __launch_bounds__(256)
pass1_k(const float4* __restrict__ S4, int N) {
    const int lane = threadIdx.x & 31;
    const int gwarp = blockIdx.x * (blockDim.x >> 5) + (threadIdx.x >> 5);
    const int nwarps = gridDim.x * (blockDim.x >> 5);
    const unsigned long long pol_ef = pol_evict_first();
    const unsigned long long pol_el = pol_evict_last();

    float c0 = 0.f, c1 = 0.f, c2 = 0.f, c3 = 0.f;
    unsigned* __restrict__ E8 = reinterpret_cast<unsigned*>(g_E8);

    int row = gwarp;
    for (; row + 3 * nwarps < N; row += 4 * nwarps) {
        float4 s[4];
        #pragma unroll
        for (int m = 0; m < 4; ++m)
            s[m] = ldg_hint_f4(&S4[(size_t)(row + m * nwarps) * 32 + lane], pol_ef);

        float e[4][4], p[4];
        #pragma unroll
        for (int m = 0; m < 4; ++m) {
            e[m][0] = __expf(s[m].x); e[m][1] = __expf(s[m].y);
            e[m][2] = __expf(s[m].z); e[m][3] = __expf(s[m].w);
            unsigned pk = (unsigned)pack_fp8x2(e[m][1], e[m][0])
                        | ((unsigned)pack_fp8x2(e[m][3], e[m][2]) << 16);
            stg_hint_u32(&E8[(size_t)(row + m * nwarps) * 32 + lane], pk, pol_el);
            p[m] = (e[m][0] + e[m][1]) + (e[m][2] + e[m][3]);
        }
        #pragma unroll
        for (int o = 16; o; o >>= 1) {
            #pragma unroll
            for (int m = 0; m < 4; ++m)
                p[m] += __shfl_xor_sync(0xffffffffu, p[m], o);
        }
        #pragma unroll
        for (int m = 0; m < 4; ++m) {
            float u = 1.0f / p[m];
            c0 = fmaf(u, e[m][0], c0); c1 = fmaf(u, e[m][1], c1);
            c2 = fmaf(u, e[m][2], c2); c3 = fmaf(u, e[m][3], c3);
        }
    }
    for (; row < N; row += nwarps) {
        float4 s = ldg_hint_f4(&S4[(size_t)row * 32 + lane], pol_ef);
        float e0 = __expf(s.x), e1 = __expf(s.y), e2 = __expf(s.z), e3 = __expf(s.w);
        unsigned pk = (unsigned)pack_fp8x2(e1, e0) | ((unsigned)pack_fp8x2(e3, e2) << 16);
        stg_hint_u32(&E8[(size_t)row * 32 + lane], pk, pol_el);
        float p = (e0 + e1) + (e2 + e3);
        #pragma unroll
        for (int o = 16; o; o >>= 1) p += __shfl_xor_sync(0xffffffffu, p, o);
        float u = 1.0f / p;
        c0 = fmaf(u, e0, c0); c1 = fmaf(u, e1, c1);
        c2 = fmaf(u, e2, c2); c3 = fmaf(u, e3, c3);
    }

    __shared__ float scol[C];
    if (threadIdx.x < C) scol[threadIdx.x] = 0.0f;
    __syncthreads();
    int col = lane * 4;
    atomicAdd(&scol[col + 0], c0);
    atomicAdd(&scol[col + 1], c1);
    atomicAdd(&scol[col + 2], c2);
    atomicAdd(&scol[col + 3], c3);
    __syncthreads();
    if (threadIdx.x < C)
        atomicAdd(&g_colsum[1][threadIdx.x], scol[threadIdx.x]);
}

// ---------------------------------------------------------------------------
// Persistent kernel: iterations 2..10 on fp8 E with software grid barriers.
// 592 blocks x 256 threads, 4 blocks/SM co-resident (launch_bounds(256,4)).
// ---------------------------------------------------------------------------
__global__ void __launch_bounds__(PBLK, 4)
sinkiters_k(int N) {
    const int lane = threadIdx.x & 31;
    const int sub = lane & 7;
    const int gwarp = blockIdx.x * (PBLK >> 5) + (threadIdx.x >> 5);
    const int nwarps = PGRID * (PBLK >> 5);
    const int G = N >> 2;
    const int rem = N & 3;
    const unsigned long long pol_el = pol_evict_last();

    __shared__ float sv[C];
    __shared__ float scol[C];

    for (int t = 2; t <= NUM_ITERS; ++t) {
        if (threadIdx.x < C) {
            sv[threadIdx.x] = g_b[threadIdx.x] / __ldcg(&g_colsum[t - 1][threadIdx.x]);
            scol[threadIdx.x] = 0.0f;
        }
        __syncthreads();

        __half2 v2[8], c2[8];
        #pragma unroll
        for (int k = 0; k < 8; ++k) {
            v2[k] = __floats2half2_rn(sv[sub * 16 + 2 * k], sv[sub * 16 + 2 * k + 1]);
            c2[k] = __floats2half2_rn(0.f, 0.f);
        }

        auto process = [&](uint4 q) {
            __half2 h[8];
            h[0] = fp8x2_to_h2((unsigned short)(q.x & 0xffff));
            h[1] = fp8x2_to_h2((unsigned short)(q.x >> 16));
            h[2] = fp8x2_to_h2((unsigned short)(q.y & 0xffff));
            h[3] = fp8x2_to_h2((unsigned short)(q.y >> 16));
            h[4] = fp8x2_to_h2((unsigned short)(q.z & 0xffff));
            h[5] = fp8x2_to_h2((unsigned short)(q.z >> 16));
            h[6] = fp8x2_to_h2((unsigned short)(q.w & 0xffff));
            h[7] = fp8x2_to_h2((unsigned short)(q.w >> 16));
            __half2 pa = __hmul2(h[0], v2[0]);
            __half2 pb = __hmul2(h[4], v2[4]);
            pa = __hfma2(h[1], v2[1], pa);
            pb = __hfma2(h[5], v2[5], pb);
            pa = __hfma2(h[2], v2[2], pa);
            pb = __hfma2(h[6], v2[6], pb);
            pa = __hfma2(h[3], v2[3], pa);
            pb = __hfma2(h[7], v2[7], pb);
            pa = __hadd2(pa, pb);
            float2 pf = __half22float2(pa);
            float p = pf.x + pf.y;
            p += __shfl_xor_sync(0xffffffffu, p, 4);
            p += __shfl_xor_sync(0xffffffffu, p, 2);
            p += __shfl_xor_sync(0xffffffffu, p, 1);
            __half2 u2 = __float2half2_rn(1.0f / p);
            #pragma unroll
            for (int k = 0; k < 8; ++k)
                c2[k] = __hfma2(u2, h[k], c2[k]);
        };

        int g = gwarp;
        for (; g + 3 * nwarps < G; g += 4 * nwarps) {
            uint4 q0 = ldg_hint_u4(&g_E8[(size_t)g * 32 + lane], pol_el);
            uint4 q1 = ldg_hint_u4(&g_E8[(size_t)(g + nwarps) * 32 + lane], pol_el);
            uint4 q2 = ldg_hint_u4(&g_E8[(size_t)(g + 2 * nwarps) * 32 + lane], pol_el);
            uint4 q3 = ldg_hint_u4(&g_E8[(size_t)(g + 3 * nwarps) * 32 + lane], pol_el);
            process(q0); process(q1); process(q2); process(q3);
        }
        for (; g < G; g += nwarps)
            process(ldg_hint_u4(&g_E8[(size_t)g * 32 + lane], pol_el));

        if (gwarp < rem && lane < 8) {   // remainder rows (N % 4)
            int row = G * 4 + gwarp;
            uint4 q = g_E8[(size_t)row * 8 + sub];
            __half2 h[8];
            h[0] = fp8x2_to_h2((unsigned short)(q.x & 0xffff));
            h[1] = fp8x2_to_h2((unsigned short)(q.x >> 16));
            h[2] = fp8x2_to_h2((unsigned short)(q.y & 0xffff));
            h[3] = fp8x2_to_h2((unsigned short)(q.y >> 16));
            h[4] = fp8x2_to_h2((unsigned short)(q.z & 0xffff));
            h[5] = fp8x2_to_h2((unsigned short)(q.z >> 16));
            h[6] = fp8x2_to_h2((unsigned short)(q.w & 0xffff));
            h[7] = fp8x2_to_h2((unsigned short)(q.w >> 16));
            float p = 0.f;
            #pragma unroll
            for (int k = 0; k < 8; ++k) {
                float2 pr = __half22float2(__hmul2(h[k], v2[k]));
                p += pr.x + pr.y;
            }
            p += __shfl_xor_sync(0x000000ffu, p, 4);
            p += __shfl_xor_sync(0x000000ffu, p, 2);
            p += __shfl_xor_sync(0x000000ffu, p, 1);
            __half2 u2 = __float2half2_rn(1.0f / p);
            #pragma unroll
            for (int k = 0; k < 8; ++k)
                c2[k] = __hfma2(u2, h[k], c2[k]);
        }

        // Reduce c2 across the 4 row-slots of the warp (lanes l, l+8, l+16, l+24).
        #pragma unroll
        for (int k = 0; k < 8; ++k) {
            unsigned pk = *reinterpret_cast<unsigned*>(&c2[k]);
            unsigned o1 = __shfl_xor_sync(0xffffffffu, pk, 8);
            __half2 s = __hadd2(c2[k], *reinterpret_cast<__half2*>(&o1));
            unsigned ps = *reinterpret_cast<unsigned*>(&s);
            unsigned o2 = __shfl_xor_sync(0xffffffffu, ps, 16);
            c2[k] = __hadd2(s, *reinterpret_cast<__half2*>(&o2));
        }
        if (lane < 8) {
            #pragma unroll
            for (int k = 0; k < 8; ++k) {
                float2 cf = __half22float2(c2[k]);
                atomicAdd(&scol[sub * 16 + 2 * k], cf.x);
                atomicAdd(&scol[sub * 16 + 2 * k + 1], cf.y);
            }
        }
        __syncthreads();
        if (threadIdx.x < C)
            atomicAdd(&g_colsum[t][threadIdx.x], scol[threadIdx.x]);

        // Grid barrier (skip after the last iteration).
        if (t < NUM_ITERS) {
            __threadfence();          // publish this block's colsum atomics
            __syncthreads();
            if (threadIdx.x == 0) {
                atomicAdd(&g_arrive, 1);
                const int target = (t - 1) * PGRID;
                int cur;
                do {
                    asm volatile("ld.global.cg.s32 %0, [%1];" : "=r"(cur) : "l"(&g_arrive));
                    if (cur < target) __nanosleep(64);
                } while (cur < target);
                __threadfence();
            }
            __syncthreads();
        }
    }
}

// ---------------------------------------------------------------------------
// Final: P_ij = u_i * exp(S_ij) * v10[j], u_i = 1/sum_j exp(S_ij)*v9[j].
// fp32 S for output precision. Unroll x4, streaming cache hints.
// ---------------------------------------------------------------------------
__global__ void __launch_bounds__(256)
final_k(const float4* __restrict__ S4, float4* __restrict__ out, int N) {
    const int lane = threadIdx.x & 31;
    const int gwarp = blockIdx.x * (blockDim.x >> 5) + (threadIdx.x >> 5);
    const int nwarps = gridDim.x * (blockDim.x >> 5);
    const unsigned long long pol_ef = pol_evict_first();

    __shared__ float sv9[C], sv10[C];
    if (threadIdx.x < C) {
        sv9[threadIdx.x]  = g_b[threadIdx.x] / __ldcg(&g_colsum[NUM_ITERS - 1][threadIdx.x]);
        sv10[threadIdx.x] = g_b[threadIdx.x] / __ldcg(&g_colsum[NUM_ITERS][threadIdx.x]);
    }
    __syncthreads();

    float4 v9  = reinterpret_cast<const float4*>(sv9)[lane];
    float4 v10 = reinterpret_cast<const float4*>(sv10)[lane];

    int row = gwarp;
    for (; row + 3 * nwarps < N; row += 4 * nwarps) {
        float4 s[4];
        #pragma unroll
        for (int m = 0; m < 4; ++m)
            s[m] = ldg_hint_f4(&S4[(size_t)(row + m * nwarps) * 32 + lane], pol_ef);

        float e[4][4], p[4];
        #pragma unroll
        for (int m = 0; m < 4; ++m) {
            e[m][0] = __expf(s[m].x); e[m][1] = __expf(s[m].y);
            e[m][2] = __expf(s[m].z); e[m][3] = __expf(s[m].w);
            p[m] = fmaf(e[m][0], v9.x, fmaf(e[m][1], v9.y, fmaf(e[m][2], v9.z, e[m][3] * v9.w)));
        }
        #pragma unroll
        for (int o = 16; o; o >>= 1) {
            #pragma unroll
            for (int m = 0; m < 4; ++m)
                p[m] += __shfl_xor_sync(0xffffffffu, p[m], o);
        }
        #pragma unroll
        for (int m = 0; m < 4; ++m) {
            float u = 1.0f / p[m];
            float4 o4;
            o4.x = u * e[m][0] * v10.x; o4.y = u * e[m][1] * v10.y;
            o4.z = u * e[m][2] * v10.z; o4.w = u * e[m][3] * v10.w;
            stg_hint_f4(&out[(size_t)(row + m * nwarps) * 32 + lane], o4, pol_ef);
        }
    }
    for (; row < N; row += nwarps) {
        float4 s = ldg_hint_f4(&S4[(size_t)row * 32 + lane], pol_ef);
        float e0 = __expf(s.x), e1 = __expf(s.y), e2 = __expf(s.z), e3 = __expf(s.w);
        float p = fmaf(e0, v9.x, fmaf(e1, v9.y, fmaf(e2, v9.z, e3 * v9.w)));
        #pragma unroll
        for (int o = 16; o; o >>= 1) p += __shfl_xor_sync(0xffffffffu, p, o);
        float u = 1.0f / p;
        float4 o4;
        o4.x = u * e0 * v10.x; o4.y = u * e1 * v10.y;
        o4.z = u * e2 * v10.z; o4.w = u * e3 * v10.w;
        stg_hint_f4(&out[(size_t)row * 32 + lane], o4, pol_ef);
    }
}

// ---------------------------------------------------------------------------
extern "C" void kernel_launch(void* const* d_in, const int* in_sizes, int n_in,
                              void* d_out, int out_size) {
    const float* S        = (const float*)d_in[2];
    const float* ratios   = (const float*)d_in[3];
    const int*   totalnum = (const int*)d_in[5];
    const int N = in_sizes[2] / C;

    init_k<<<1, C>>>(ratios, totalnum);
    pass1_k<<<1184, 256>>>((const float4*)S, N);      // iteration 1 + E8 store
    sinkiters_k<<<PGRID, PBLK>>>(N);                  // iterations 2..10 (persistent)
    final_k<<<1184, 256>>>((const float4*)S, (float4*)d_out, N);
}

// round 8
// speedup vs baseline: 3.1288x; 1.4295x over previous
#include <cuda_runtime.h>
#include <cuda_fp16.h>

#define C 128
#define NUM_ITERS 10
#define MAXN 500000
#define PGRID 592          // 4 blocks/SM * 148 SMs co-resident
#define PBLK  256
#define STAGES 4
#define CONV_TOL 1e-4f

// Scratch (__device__ globals, no allocation).
__device__ float g_b[C];
__device__ float g_colsum[NUM_ITERS + 1][C];
__device__ int   g_arrive;                       // monotonic grid-barrier counter
__device__ int   g_tA, g_tB;                     // colsum indices for final pass
__device__ uint4 g_E8[(size_t)MAXN * 8];         // E = exp(S) fp8 e4m3, 128 B/row

// ---- fp8 helpers ------------------------------------------------------------
__device__ __forceinline__ unsigned short pack_fp8x2(float hi, float lo) {
    unsigned short v;
    asm("cvt.rn.satfinite.e4m3x2.f32 %0, %1, %2;" : "=h"(v) : "f"(hi), "f"(lo));
    return v;
}
__device__ __forceinline__ __half2 fp8x2_to_h2(unsigned short p) {
    unsigned r;
    asm("cvt.rn.f16x2.e4m3x2 %0, %1;" : "=r"(r) : "h"(p));
    return *reinterpret_cast<__half2*>(&r);
}

// ---- cache-policy helpers ---------------------------------------------------
__device__ __forceinline__ unsigned long long pol_evict_last() {
    unsigned long long p;
    asm("createpolicy.fractional.L2::evict_last.b64 %0, 1.0;" : "=l"(p));
    return p;
}
__device__ __forceinline__ unsigned long long pol_evict_first() {
    unsigned long long p;
    asm("createpolicy.fractional.L2::evict_first.b64 %0, 1.0;" : "=l"(p));
    return p;
}
__device__ __forceinline__ float4 ldg_hint_f4(const float4* p, unsigned long long pol) {
    float4 q;
    asm volatile("ld.global.nc.L2::cache_hint.v4.f32 {%0,%1,%2,%3}, [%4], %5;"
                 : "=f"(q.x), "=f"(q.y), "=f"(q.z), "=f"(q.w) : "l"(p), "l"(pol));
    return q;
}
__device__ __forceinline__ void stg_hint_u32(unsigned* p, unsigned v, unsigned long long pol) {
    asm volatile("st.global.L2::cache_hint.u32 [%0], %1, %2;"
                 :: "l"(p), "r"(v), "l"(pol) : "memory");
}
__device__ __forceinline__ void stg_hint_f4(float4* p, float4 v, unsigned long long pol) {
    asm volatile("st.global.L2::cache_hint.v4.f32 [%0], {%1,%2,%3,%4}, %5;"
                 :: "l"(p), "f"(v.x), "f"(v.y), "f"(v.z), "f"(v.w), "l"(pol) : "memory");
}

// ---- cp.async helpers -------------------------------------------------------
__device__ __forceinline__ void cp_async16(unsigned dst, const void* src) {
    asm volatile("cp.async.cg.shared.global [%0], [%1], 16;" :: "r"(dst), "l"(src) : "memory");
}
#define CP_COMMIT() asm volatile("cp.async.commit_group;" ::: "memory")
#define CP_WAIT(n)  asm volatile("cp.async.wait_group %0;" :: "n"(n) : "memory")
__device__ __forceinline__ uint4 lds128(unsigned addr) {
    uint4 q;
    asm volatile("ld.shared.v4.u32 {%0,%1,%2,%3}, [%4];"
                 : "=r"(q.x), "=r"(q.y), "=r"(q.z), "=r"(q.w) : "r"(addr));
    return q;
}

// ---------------------------------------------------------------------------
__global__ void init_k(const float* __restrict__ ratios,
                       const int* __restrict__ total_num) {
    int j = threadIdx.x;
    float tn = (float)(*total_num);
    g_b[j] = ratios[j] * tn;
    #pragma unroll
    for (int t = 0; t <= NUM_ITERS; ++t) g_colsum[t][j] = 0.0f;
    if (j == 0) { g_arrive = 0; g_tA = NUM_ITERS - 1; g_tB = NUM_ITERS; }
}

// ---------------------------------------------------------------------------
// Pass 1 (iteration 1, v0=1) fused with E = exp(S) -> fp8 store. Unroll x4.
// ---------------------------------------------------------------------------
__global__ void __launch_bounds__(256)
pass1_k(const float4* __restrict__ S4, int N) {
    const int lane = threadIdx.x & 31;
    const int gwarp = blockIdx.x * (blockDim.x >> 5) + (threadIdx.x >> 5);
    const int nwarps = gridDim.x * (blockDim.x >> 5);
    const unsigned long long pol_ef = pol_evict_first();
    const unsigned long long pol_el = pol_evict_last();

    float c0 = 0.f, c1 = 0.f, c2 = 0.f, c3 = 0.f;
    unsigned* __restrict__ E8 = reinterpret_cast<unsigned*>(g_E8);

    int row = gwarp;
    for (; row + 3 * nwarps < N; row += 4 * nwarps) {
        float4 s[4];
        #pragma unroll
        for (int m = 0; m < 4; ++m)
            s[m] = ldg_hint_f4(&S4[(size_t)(row + m * nwarps) * 32 + lane], pol_ef);

        float e[4][4], p[4];
        #pragma unroll
        for (int m = 0; m < 4; ++m) {
            e[m][0] = __expf(s[m].x); e[m][1] = __expf(s[m].y);
            e[m][2] = __expf(s[m].z); e[m][3] = __expf(s[m].w);
            unsigned pk = (unsigned)pack_fp8x2(e[m][1], e[m][0])
                        | ((unsigned)pack_fp8x2(e[m][3], e[m][2]) << 16);
            stg_hint_u32(&E8[(size_t)(row + m * nwarps) * 32 + lane], pk, pol_el);
            p[m] = (e[m][0] + e[m][1]) + (e[m][2] + e[m][3]);
        }
        #pragma unroll
        for (int o = 16; o; o >>= 1) {
            #pragma unroll
            for (int m = 0; m < 4; ++m)
                p[m] += __shfl_xor_sync(0xffffffffu, p[m], o);
        }
        #pragma unroll
        for (int m = 0; m < 4; ++m) {
            float u = 1.0f / p[m];
            c0 = fmaf(u, e[m][0], c0); c1 = fmaf(u, e[m][1], c1);
            c2 = fmaf(u, e[m][2], c2); c3 = fmaf(u, e[m][3], c3);
        }
    }
    for (; row < N; row += nwarps) {
        float4 s = ldg_hint_f4(&S4[(size_t)row * 32 + lane], pol_ef);
        float e0 = __expf(s.x), e1 = __expf(s.y), e2 = __expf(s.z), e3 = __expf(s.w);
        unsigned pk = (unsigned)pack_fp8x2(e1, e0) | ((unsigned)pack_fp8x2(e3, e2) << 16);
        stg_hint_u32(&E8[(size_t)row * 32 + lane], pk, pol_el);
        float p = (e0 + e1) + (e2 + e3);
        #pragma unroll
        for (int o = 16; o; o >>= 1) p += __shfl_xor_sync(0xffffffffu, p, o);
        float u = 1.0f / p;
        c0 = fmaf(u, e0, c0); c1 = fmaf(u, e1, c1);
        c2 = fmaf(u, e2, c2); c3 = fmaf(u, e3, c3);
    }

    __shared__ float scol[C];
    if (threadIdx.x < C) scol[threadIdx.x] = 0.0f;
    __syncthreads();
    int col = lane * 4;
    atomicAdd(&scol[col + 0], c0);
    atomicAdd(&scol[col + 1], c1);
    atomicAdd(&scol[col + 2], c2);
    atomicAdd(&scol[col + 3], c3);
    __syncthreads();
    if (threadIdx.x < C)
        atomicAdd(&g_colsum[1][threadIdx.x], scol[threadIdx.x]);
}

// ---------------------------------------------------------------------------
// Persistent kernel: iterations 2..10, cp.async 4-stage pipeline, grid
// barriers between iterations, deterministic convergence early-exit.
// ---------------------------------------------------------------------------
__global__ void __launch_bounds__(PBLK, 4)
sinkiters_k(int N) {
    const int lane = threadIdx.x & 31;
    const int sub = lane & 7;
    const int wid = threadIdx.x >> 5;
    const int gwarp = blockIdx.x * (PBLK >> 5) + wid;
    const int nwarps = PGRID * (PBLK >> 5);
    const int G = N >> 2;                  // groups of 4 rows (512 B)
    const int rem = N & 3;

    __shared__ float sv[C];
    __shared__ float scol[C];
    __shared__ __align__(16) unsigned char pipe[PBLK / 32][STAGES * 512];

    const unsigned sbuf =
        (unsigned)__cvta_generic_to_shared(&pipe[wid][0]) + (unsigned)lane * 16;
    // warp's number of groups (grid-stride over G with stride nwarps)
    const int total = (gwarp < G) ? ((G - gwarp - 1) / nwarps + 1) : 0;

    int tlast = NUM_ITERS;
    for (int t = 2; t <= NUM_ITERS; ++t) {
        // v_t-1 setup + convergence vote (identical in every block).
        int bigflag = 0;
        if (threadIdx.x < C) {
            float vn = g_b[threadIdx.x] / __ldcg(&g_colsum[t - 1][threadIdx.x]);
            sv[threadIdx.x] = vn;
            scol[threadIdx.x] = 0.0f;
            if (t >= 3) {
                float vo = g_b[threadIdx.x] / __ldcg(&g_colsum[t - 2][threadIdx.x]);
                bigflag = fabsf(vn - vo) > CONV_TOL * vn;
            }
        }
        int moving = __syncthreads_or(bigflag);
        if (t >= 3 && !moving) {
            tlast = t - 1;
            if (blockIdx.x == 0 && threadIdx.x == 0) {
                g_tA = tlast; g_tB = tlast;
                __threadfence();
            }
            break;                          // all blocks break together
        }

        __half2 v2[8], c2[8];
        #pragma unroll
        for (int k = 0; k < 8; ++k) {
            v2[k] = __floats2half2_rn(sv[sub * 16 + 2 * k], sv[sub * 16 + 2 * k + 1]);
            c2[k] = __floats2half2_rn(0.f, 0.f);
        }

        auto process = [&](uint4 q) {
            __half2 h[8];
            h[0] = fp8x2_to_h2((unsigned short)(q.x & 0xffff));
            h[1] = fp8x2_to_h2((unsigned short)(q.x >> 16));
            h[2] = fp8x2_to_h2((unsigned short)(q.y & 0xffff));
            h[3] = fp8x2_to_h2((unsigned short)(q.y >> 16));
            h[4] = fp8x2_to_h2((unsigned short)(q.z & 0xffff));
            h[5] = fp8x2_to_h2((unsigned short)(q.z >> 16));
            h[6] = fp8x2_to_h2((unsigned short)(q.w & 0xffff));
            h[7] = fp8x2_to_h2((unsigned short)(q.w >> 16));
            __half2 pa = __hmul2(h[0], v2[0]);
            __half2 pb = __hmul2(h[4], v2[4]);
            pa = __hfma2(h[1], v2[1], pa);
            pb = __hfma2(h[5], v2[5], pb);
            pa = __hfma2(h[2], v2[2], pa);
            pb = __hfma2(h[6], v2[6], pb);
            pa = __hfma2(h[3], v2[3], pa);
            pb = __hfma2(h[7], v2[7], pb);
            pa = __hadd2(pa, pb);
            float2 pf = __half22float2(pa);
            float p = pf.x + pf.y;
            p += __shfl_xor_sync(0xffffffffu, p, 4);
            p += __shfl_xor_sync(0xffffffffu, p, 2);
            p += __shfl_xor_sync(0xffffffffu, p, 1);
            __half2 u2 = __float2half2_rn(1.0f / p);
            #pragma unroll
            for (int k = 0; k < 8; ++k)
                c2[k] = __hfma2(u2, h[k], c2[k]);
        };

        // cp.async pipeline: always STAGES groups in flight per warp.
        int j = 0;
        #pragma unroll
        for (int s = 0; s < STAGES; ++s) {
            if (j < total)
                cp_async16(sbuf + s * 512,
                           &g_E8[(size_t)(gwarp + (size_t)j * nwarps) * 32 + lane]);
            CP_COMMIT();
            ++j;
        }
        for (int k = 0; k < total; ++k) {
            CP_WAIT(STAGES - 1);
            uint4 q = lds128(sbuf + (k & (STAGES - 1)) * 512);
            process(q);
            if (j < total)
                cp_async16(sbuf + (j & (STAGES - 1)) * 512,
                           &g_E8[(size_t)(gwarp + (size_t)j * nwarps) * 32 + lane]);
            CP_COMMIT();
            ++j;
        }
        CP_WAIT(0);

        if (gwarp < rem && lane < 8) {   // remainder rows (N % 4)
            int row = G * 4 + gwarp;
            uint4 q = g_E8[(size_t)row * 8 + sub];
            __half2 h[8];
            h[0] = fp8x2_to_h2((unsigned short)(q.x & 0xffff));
            h[1] = fp8x2_to_h2((unsigned short)(q.x >> 16));
            h[2] = fp8x2_to_h2((unsigned short)(q.y & 0xffff));
            h[3] = fp8x2_to_h2((unsigned short)(q.y >> 16));
            h[4] = fp8x2_to_h2((unsigned short)(q.z & 0xffff));
            h[5] = fp8x2_to_h2((unsigned short)(q.z >> 16));
            h[6] = fp8x2_to_h2((unsigned short)(q.w & 0xffff));
            h[7] = fp8x2_to_h2((unsigned short)(q.w >> 16));
            float p = 0.f;
            #pragma unroll
            for (int k = 0; k < 8; ++k) {
                float2 pr = __half22float2(__hmul2(h[k], v2[k]));
                p += pr.x + pr.y;
            }
            p += __shfl_xor_sync(0x000000ffu, p, 4);
            p += __shfl_xor_sync(0x000000ffu, p, 2);
            p += __shfl_xor_sync(0x000000ffu, p, 1);
            __half2 u2 = __float2half2_rn(1.0f / p);
            #pragma unroll
            for (int k = 0; k < 8; ++k)
                c2[k] = __hfma2(u2, h[k], c2[k]);
        }

        // Reduce c2 across the 4 row-slots of the warp.
        #pragma unroll
        for (int k = 0; k < 8; ++k) {
            unsigned pk = *reinterpret_cast<unsigned*>(&c2[k]);
            unsigned o1 = __shfl_xor_sync(0xffffffffu, pk, 8);
            __half2 s = __hadd2(c2[k], *reinterpret_cast<__half2*>(&o1));
            unsigned ps = *reinterpret_cast<unsigned*>(&s);
            unsigned o2 = __shfl_xor_sync(0xffffffffu, ps, 16);
            c2[k] = __hadd2(s, *reinterpret_cast<__half2*>(&o2));
        }
        if (lane < 8) {
            #pragma unroll
            for (int k = 0; k < 8; ++k) {
                float2 cf = __half22float2(c2[k]);
                atomicAdd(&scol[sub * 16 + 2 * k], cf.x);
                atomicAdd(&scol[sub * 16 + 2 * k + 1], cf.y);
            }
        }
        __syncthreads();
        if (threadIdx.x < C)
            atomicAdd(&g_colsum[t][threadIdx.x], scol[threadIdx.x]);

        // Grid barrier between iterations.
        if (t < NUM_ITERS) {
            __threadfence();
            __syncthreads();
            if (threadIdx.x == 0) {
                atomicAdd(&g_arrive, 1);
                const int target = (t - 1) * PGRID;
                int cur;
                do {
                    asm volatile("ld.global.cg.s32 %0, [%1];" : "=r"(cur) : "l"(&g_arrive));
                    if (cur < target) __nanosleep(64);
                } while (cur < target);
                __threadfence();
            }
            __syncthreads();
        }
    }
}

// ---------------------------------------------------------------------------
// Final: P_ij = u_i * exp(S_ij) * v_tB[j], u_i = 1/sum_j exp(S_ij)*v_tA[j].
// ---------------------------------------------------------------------------
__global__ void __launch_bounds__(256)
final_k(const float4* __restrict__ S4, float4* __restrict__ out, int N) {
    const int lane = threadIdx.x & 31;
    const int gwarp = blockIdx.x * (blockDim.x >> 5) + (threadIdx.x >> 5);
    const int nwarps = gridDim.x * (blockDim.x >> 5);
    const unsigned long long pol_ef = pol_evict_first();

    __shared__ float sv9[C], sv10[C];
    if (threadIdx.x < C) {
        int tA = __ldcg(&g_tA), tB = __ldcg(&g_tB);
        sv9[threadIdx.x]  = g_b[threadIdx.x] / __ldcg(&g_colsum[tA][threadIdx.x]);
        sv10[threadIdx.x] = g_b[threadIdx.x] / __ldcg(&g_colsum[tB][threadIdx.x]);
    }
    __syncthreads();

    float4 v9  = reinterpret_cast<const float4*>(sv9)[lane];
    float4 v10 = reinterpret_cast<const float4*>(sv10)[lane];

    int row = gwarp;
    for (; row + 3 * nwarps < N; row += 4 * nwarps) {
        float4 s[4];
        #pragma unroll
        for (int m = 0; m < 4; ++m)
            s[m] = ldg_hint_f4(&S4[(size_t)(row + m * nwarps) * 32 + lane], pol_ef);

        float e[4][4], p[4];
        #pragma unroll
        for (int m = 0; m < 4; ++m) {
            e[m][0] = __expf(s[m].x); e[m][1] = __expf(s[m].y);
            e[m][2] = __expf(s[m].z); e[m][3] = __expf(s[m].w);
            p[m] = fmaf(e[m][0], v9.x, fmaf(e[m][1], v9.y, fmaf(e[m][2], v9.z, e[m][3] * v9.w)));
        }
        #pragma unroll
        for (int o = 16; o; o >>= 1) {
            #pragma unroll
            for (int m = 0; m < 4; ++m)
                p[m] += __shfl_xor_sync(0xffffffffu, p[m], o);
        }
        #pragma unroll
        for (int m = 0; m < 4; ++m) {
            float u = 1.0f / p[m];
            float4 o4;
            o4.x = u * e[m][0] * v10.x; o4.y = u * e[m][1] * v10.y;
            o4.z = u * e[m][2] * v10.z; o4.w = u * e[m][3] * v10.w;
            stg_hint_f4(&out[(size_t)(row + m * nwarps) * 32 + lane], o4, pol_ef);
        }
    }
    for (; row < N; row += nwarps) {
        float4 s = ldg_hint_f4(&S4[(size_t)row * 32 + lane], pol_ef);
        float e0 = __expf(s.x), e1 = __expf(s.y), e2 = __expf(s.z), e3 = __expf(s.w);
        float p = fmaf(e0, v9.x, fmaf(e1, v9.y, fmaf(e2, v9.z, e3 * v9.w)));
        #pragma unroll
        for (int o = 16; o; o >>= 1) p += __shfl_xor_sync(0xffffffffu, p, o);
        float u = 1.0f / p;
        float4 o4;
        o4.x = u * e0 * v10.x; o4.y = u * e1 * v10.y;
        o4.z = u * e2 * v10.z; o4.w = u * e3 * v10.w;
        stg_hint_f4(&out[(size_t)row * 32 + lane], o4, pol_ef);
    }
}

// ---------------------------------------------------------------------------
extern "C" void kernel_launch(void* const* d_in, const int* in_sizes, int n_in,
                              void* d_out, int out_size) {
    const float* S        = (const float*)d_in[2];
    const float* ratios   = (const float*)d_in[3];
    const int*   totalnum = (const int*)d_in[5];
    const int N = in_sizes[2] / C;

    init_k<<<1, C>>>(ratios, totalnum);
    pass1_k<<<1184, 256>>>((const float4*)S, N);      // iteration 1 + E8 store
    sinkiters_k<<<PGRID, PBLK>>>(N);                  // iterations 2..10 (persistent)
    final_k<<<1184, 256>>>((const float4*)S, (float4*)d_out, N);
}